// round 14
// baseline (speedup 1.0000x reference)
#include <cuda_runtime.h>
#include <cuda_bf16.h>

// Problem constants (StridedSparseAttention: B=4, S=4096, D=512, STRIDE=8)
#define BB 4
#define SS 4096
#define DD 512
#define NK 512          // number of strided keys = S/8
#define KSTRIDE 8
#define DP2 256         // DD/2 (b32 pairs per row)
#define NKP2 256        // NK/2
#define PITCH 12        // smem row pitch in uints (R11-validated: cp16-aligned + LDSM-clean)

#define SCALE 0.044194173824159216f   // 1/sqrt(512)

// Scratch (device globals — no allocations allowed). uint = packed bf16x2.
__device__ unsigned g_qhi[(long)BB * SS * DP2];
__device__ unsigned g_qlo[(long)BB * SS * DP2];
__device__ unsigned g_khi[BB * NK * DP2];
__device__ unsigned g_klo[BB * NK * DP2];
__device__ unsigned g_vthi[BB * DD * NKP2];      // vT[d][c] hi
__device__ unsigned g_vtlo[BB * DD * NKP2];
__device__ unsigned g_whi[(long)BB * SS * NKP2]; // UNnormalized exp(score), bf16 hi
__device__ unsigned g_wlo[(long)BB * SS * NKP2];
// Deterministic rowsum partials: 16 slots per row = [nt(0..7)][wn(0..1)].
__device__ float g_rspart[(long)BB * SS * 16];

// ---------------------------------------------------------------------------
// helpers
// ---------------------------------------------------------------------------
__device__ __forceinline__ void split2(float x, float y, unsigned& hi, unsigned& lo) {
    __nv_bfloat16 hx = __float2bfloat16_rn(x);
    __nv_bfloat16 hy = __float2bfloat16_rn(y);
    float rx = x - __bfloat162float(hx);
    float ry = y - __bfloat162float(hy);
    __nv_bfloat162 h2; h2.x = hx; h2.y = hy;
    __nv_bfloat162 l2; l2.x = __float2bfloat16_rn(rx); l2.y = __float2bfloat16_rn(ry);
    hi = *reinterpret_cast<unsigned*>(&h2);
    lo = *reinterpret_cast<unsigned*>(&l2);
}

__device__ __forceinline__ void mma_bf16(float* d, const unsigned* a, const unsigned* b) {
    asm volatile(
        "mma.sync.aligned.m16n8k16.row.col.f32.bf16.bf16.f32 "
        "{%0,%1,%2,%3},{%4,%5,%6,%7},{%8,%9},{%0,%1,%2,%3};\n"
        : "+f"(d[0]), "+f"(d[1]), "+f"(d[2]), "+f"(d[3])
        : "r"(a[0]), "r"(a[1]), "r"(a[2]), "r"(a[3]), "r"(b[0]), "r"(b[1]));
}

__device__ __forceinline__ void ldsm_x4(unsigned& r0, unsigned& r1,
                                        unsigned& r2, unsigned& r3, unsigned saddr) {
    asm volatile("ldmatrix.sync.aligned.m8n8.x4.shared.b16 {%0,%1,%2,%3}, [%4];"
                 : "=r"(r0), "=r"(r1), "=r"(r2), "=r"(r3) : "r"(saddr));
}

__device__ __forceinline__ void cp16(unsigned* smem, const unsigned* gmem) {
    unsigned s = (unsigned)__cvta_generic_to_shared(smem);
    asm volatile("cp.async.cg.shared.global [%0], [%1], 16;\n" :: "r"(s), "l"(gmem));
}
#define CP_COMMIT() asm volatile("cp.async.commit_group;\n")
#define CP_WAIT1()  asm volatile("cp.async.wait_group 1;\n")
#define CP_WAIT0()  asm volatile("cp.async.wait_group 0;\n")

// Deterministic rowsum: fixed-order reduction over the valid partial slots.
__device__ __forceinline__ float row_sum(long row, int i) {
    const int nv = ((i | 127) >> 9) + 1;         // valid nt tiles for this row
    const float* p = &g_rspart[row * 16];
    float s = 0.f;
    for (int j = 0; j < 2 * nv; j++) s += p[j];
    return s;
}

// ---------------------------------------------------------------------------
// Fused prep (one launch, independent block groups):
//   blocks [0,4096):    q -> hi/lo split; strided k -> khi/klo
//   blocks [4096,5120): strided v -> transposed vT[d][c] hi/lo
//   blocks [5120,5632): mask rows of d_out (streaming stores)
// ---------------------------------------------------------------------------
__global__ __launch_bounds__(256) void prep_fused_kernel(
    const float* __restrict__ q, const float* __restrict__ k,
    const float* __restrict__ v, float* __restrict__ mask, int full)
{
    __shared__ float sm[32][33];
    const int bx = blockIdx.x;

    if (bx < 4096) {
        const long NQ  = (long)BB * SS * DP2;
        const long NKU = (long)BB * NK * DP2;
        const long str = 4096L * 256;
        long t0 = (long)bx * 256 + threadIdx.x;

        for (long t = t0; t < NQ; t += str) {
            float2 f = reinterpret_cast<const float2*>(q)[t];
            unsigned hi, lo; split2(f.x, f.y, hi, lo);
            g_qhi[t] = hi; g_qlo[t] = lo;
        }
        for (long t = t0; t < NKU; t += str) {
            int b  = (int)(t / (NK * DP2));
            int r  = (int)((t / DP2) % NK);
            int dq = (int)(t % DP2);
            float2 f = reinterpret_cast<const float2*>(k)[((long)b * SS + KSTRIDE * r) * DP2 + dq];
            unsigned hi, lo; split2(f.x, f.y, hi, lo);
            g_khi[t] = hi; g_klo[t] = lo;
        }
    } else if (bx < 5120) {
        // V transpose: 32x32 tile. decode (b, d-tile, c-tile)
        const int t  = bx - 4096;
        const int b  = t >> 8;
        const int rem = t & 255;
        const int c0 = (rem & 15) * 32;
        const int d0 = (rem >> 4) * 32;
        const int tid = threadIdx.x;
        const int r = tid >> 3;      // 0..31
        const int j = tid & 7;       // 0..7

        float4 f = *reinterpret_cast<const float4*>(
            v + ((long)b * SS + KSTRIDE * (c0 + r)) * DD + d0 + 4 * j);
        sm[r][4 * j + 0] = f.x; sm[r][4 * j + 1] = f.y;
        sm[r][4 * j + 2] = f.z; sm[r][4 * j + 3] = f.w;
        __syncthreads();

        float v0 = sm[4 * j + 0][r], v1 = sm[4 * j + 1][r];
        float v2 = sm[4 * j + 2][r], v3 = sm[4 * j + 3][r];
        unsigned h0, l0, h1, l1;
        split2(v0, v1, h0, l0);
        split2(v2, v3, h1, l1);
        long base = ((long)b * DD + d0 + r) * NKP2 + (c0 >> 1) + 2 * j;
        g_vthi[base] = h0; g_vthi[base + 1] = h1;
        g_vtlo[base] = l0; g_vtlo[base + 1] = l1;
    } else if (full) {
        // mask rows: one warp per row, streaming stores (never re-read)
        const int i    = (bx - 5120) * 8 + (threadIdx.x >> 5);   // 0..S-1
        const int lane = threadIdx.x & 31;
        float4* mrow = reinterpret_cast<float4*>(mask + (long)i * SS);
        const int thr = i >> 2;                  // t <= thr && t even -> 1
        const bool even = (lane & 1) == 0;
#pragma unroll 4
        for (int gg = 0; gg < 32; gg++) {
            int t4 = lane + 32 * gg;
            float x = (even && t4 <= thr) ? 1.0f : 0.f;
            __stcs(&mrow[t4], make_float4(x, 0.f, 0.f, 0.f));
        }
    }
}

// ---------------------------------------------------------------------------
// QK GEMM, split-bf16 mma, 2-stage cp.async pipeline, k16 chunks, ldmatrix.
// CTA 128(i) x 64(c), 8 warps (4M x 2N), warp tile 32x32.
// Epilogue writes UNnormalized whi/wlo (causal-zeroed) + rowsum partials.
// ---------------------------------------------------------------------------
__global__ __launch_bounds__(256) void qk_mma_kernel()
{
    const int b  = blockIdx.z;
    const int mt = blockIdx.y;
    const int nt = blockIdx.x;
    const int i0 = mt * 128;
    const int c0 = nt * 64;
    if (8 * c0 > i0 + 127) return;   // fully masked tile

    __shared__ unsigned sA[2][2][128 * PITCH];   // [stage][hi/lo]
    __shared__ unsigned sB[2][2][64 * PITCH];

    const int tid  = threadIdx.x;
    const int lane = tid & 31;
    const int wid  = tid >> 5;
    const int wm   = wid & 3;
    const int wn   = wid >> 2;
    const int g    = lane >> 2;
    const int tq   = lane & 3;

    const unsigned* qh = g_qhi + ((long)b * SS + i0) * DP2;
    const unsigned* ql = g_qlo + ((long)b * SS + i0) * DP2;
    const unsigned* kh = g_khi + ((long)b * NK + c0) * DP2;
    const unsigned* kl = g_klo + ((long)b * NK + c0) * DP2;

    const int lr = tid >> 1;          // 0..127
    const int lc = (tid & 1) * 4;     // 0 or 4

    const unsigned lo16  = ((lane & 15) * PITCH + (lane >> 4) * 4) * 4u;
    const unsigned baseA = (unsigned)__cvta_generic_to_shared(&sA[0][0][0]);
    const unsigned baseB = (unsigned)__cvta_generic_to_shared(&sB[0][0][0]);

    float acc[2][4][4];
#pragma unroll
    for (int m = 0; m < 2; m++)
#pragma unroll
        for (int n = 0; n < 4; n++)
#pragma unroll
            for (int e = 0; e < 4; e++) acc[m][n][e] = 0.f;

#define QK_LOAD(ch, st)                                                          \
    do {                                                                         \
        int kb = (ch) * 8;                                                       \
        cp16(&sA[st][0][lr * PITCH + lc], qh + (long)lr * DP2 + kb + lc);        \
        cp16(&sA[st][1][lr * PITCH + lc], ql + (long)lr * DP2 + kb + lc);        \
        if (tid < 128) {                                                         \
            cp16(&sB[st][0][lr * PITCH + lc], kh + (long)lr * DP2 + kb + lc);    \
            cp16(&sB[st][1][lr * PITCH + lc], kl + (long)lr * DP2 + kb + lc);    \
        }                                                                        \
    } while (0)

    QK_LOAD(0, 0); CP_COMMIT();

    for (int ch = 0; ch < 32; ch++) {
        const int st = ch & 1;
        if (ch + 1 < 32) { QK_LOAD(ch + 1, st ^ 1); CP_COMMIT(); CP_WAIT1(); }
        else             { CP_WAIT0(); }
        __syncthreads();

        unsigned Ah[2][4], Al[2][4], Bh[4][2], Bl[4][2];
#pragma unroll
        for (int m = 0; m < 2; m++) {
            unsigned rb = (unsigned)(wm * 32 + m * 16) * (PITCH * 4u);
            ldsm_x4(Ah[m][0], Ah[m][1], Ah[m][2], Ah[m][3],
                    baseA + (st * 2 + 0) * (128 * PITCH * 4u) + rb + lo16);
            ldsm_x4(Al[m][0], Al[m][1], Al[m][2], Al[m][3],
                    baseA + (st * 2 + 1) * (128 * PITCH * 4u) + rb + lo16);
        }
#pragma unroll
        for (int p = 0; p < 2; p++) {
            unsigned rb = (unsigned)(wn * 32 + p * 16) * (PITCH * 4u);
            ldsm_x4(Bh[2 * p][0], Bh[2 * p + 1][0], Bh[2 * p][1], Bh[2 * p + 1][1],
                    baseB + (st * 2 + 0) * (64 * PITCH * 4u) + rb + lo16);
            ldsm_x4(Bl[2 * p][0], Bl[2 * p + 1][0], Bl[2 * p][1], Bl[2 * p + 1][1],
                    baseB + (st * 2 + 1) * (64 * PITCH * 4u) + rb + lo16);
        }
#pragma unroll
        for (int m = 0; m < 2; m++)
#pragma unroll
            for (int n = 0; n < 4; n++) {
                mma_bf16(acc[m][n], Ah[m], Bh[n]);
                mma_bf16(acc[m][n], Ah[m], Bl[n]);
                mma_bf16(acc[m][n], Al[m], Bh[n]);
            }
        __syncthreads();
    }
#undef QK_LOAD

    // epilogue: exp + causal predicate -> bf16 hi/lo; rowsum partial per (row,nt,wn)
#pragma unroll
    for (int m = 0; m < 2; m++) {
        int ia = i0 + wm * 32 + m * 16 + g;
        int ib = ia + 8;
        float p0 = 0.f, p1 = 0.f;
#pragma unroll
        for (int n = 0; n < 4; n++) {
            int ca = c0 + wn * 32 + n * 8 + 2 * tq;
            float w0 = (KSTRIDE * ca <= ia)       ? __expf(acc[m][n][0] * SCALE) : 0.f;
            float w1 = (KSTRIDE * (ca + 1) <= ia) ? __expf(acc[m][n][1] * SCALE) : 0.f;
            unsigned hi, lo; split2(w0, w1, hi, lo);
            long u0 = ((long)b * SS + ia) * NKP2 + (ca >> 1);
            g_whi[u0] = hi; g_wlo[u0] = lo;
            float w2 = (KSTRIDE * ca <= ib)       ? __expf(acc[m][n][2] * SCALE) : 0.f;
            float w3 = (KSTRIDE * (ca + 1) <= ib) ? __expf(acc[m][n][3] * SCALE) : 0.f;
            split2(w2, w3, hi, lo);
            long u1 = ((long)b * SS + ib) * NKP2 + (ca >> 1);
            g_whi[u1] = hi; g_wlo[u1] = lo;
            p0 += w0 + w1;
            p1 += w2 + w3;
        }
        p0 += __shfl_xor_sync(0xFFFFFFFFu, p0, 1);
        p0 += __shfl_xor_sync(0xFFFFFFFFu, p0, 2);
        p1 += __shfl_xor_sync(0xFFFFFFFFu, p1, 1);
        p1 += __shfl_xor_sync(0xFFFFFFFFu, p1, 2);
        if (tq == 0) {
            g_rspart[((long)b * SS + ia) * 16 + nt * 2 + wn] = p0;
            g_rspart[((long)b * SS + ib) * 16 + nt * 2 + wn] = p1;
        }
    }
}

// ---------------------------------------------------------------------------
// Fused output kernel:
//   blocks [0,2048):    attn rows of d_out (one warp per row, streaming stores)
//   blocks [2048,3072): PV GEMM tiles (cp.async + ldmatrix, heavy first)
// attn (DRAM-bound) scheduled first so PV (tensor-bound) backfills under it.
// ---------------------------------------------------------------------------
__global__ __launch_bounds__(256) void out_fused_kernel(
    float* __restrict__ out, float* __restrict__ attn, int full)
{
    __shared__ unsigned su[9216];   // 36864 B union: pv(sA 24576 + sB 12288) / attn(16384)

    if (blockIdx.x >= 2048) {
        // ------------------ PV branch ------------------
        const int idx = blockIdx.x - 2048;
        const int b   = idx >> 8;
        const int rem = idx & 255;
        const int nt  = rem & 7;
        const int mt  = 31 - (rem >> 3);   // heavy tiles first
        const int i0  = mt * 128;
        const int d0  = nt * 64;

#define SA(st, h, i) su[((st) * 2 + (h)) * 1536 + (i)]
#define SB(st, h, i) su[6144 + ((st) * 2 + (h)) * 768 + (i)]

        const int tid  = threadIdx.x;
        const int lane = tid & 31;
        const int wid  = tid >> 5;
        const int wm   = wid & 3;
        const int wn   = wid >> 2;
        const int g    = lane >> 2;
        const int tq   = lane & 3;

        const unsigned* wh = g_whi + ((long)b * SS + i0) * NKP2;
        const unsigned* wl = g_wlo + ((long)b * SS + i0) * NKP2;
        const unsigned* vh = g_vthi + ((long)b * DD + d0) * NKP2;
        const unsigned* vl = g_vtlo + ((long)b * DD + d0) * NKP2;

        const int lr = tid >> 1;
        const int lc = (tid & 1) * 4;

        const unsigned lo16   = ((lane & 15) * PITCH + (lane >> 4) * 4) * 4u;
        const unsigned baseSU = (unsigned)__cvta_generic_to_shared(&su[0]);

        float acc[2][4][4];
#pragma unroll
        for (int m = 0; m < 2; m++)
#pragma unroll
            for (int n = 0; n < 4; n++)
#pragma unroll
                for (int e = 0; e < 4; e++) acc[m][n][e] = 0.f;

        const int nch = mt + 1;   // k16 chunks with any valid key (<=32)

#define PV_LOAD(ch, st)                                                          \
    do {                                                                         \
        int kb = (ch) * 8;                                                       \
        cp16(&SA(st, 0, lr * PITCH + lc), wh + (long)lr * NKP2 + kb + lc);       \
        cp16(&SA(st, 1, lr * PITCH + lc), wl + (long)lr * NKP2 + kb + lc);       \
        if (tid < 128) {                                                         \
            cp16(&SB(st, 0, lr * PITCH + lc), vh + (long)lr * NKP2 + kb + lc);   \
            cp16(&SB(st, 1, lr * PITCH + lc), vl + (long)lr * NKP2 + kb + lc);   \
        }                                                                        \
    } while (0)

        PV_LOAD(0, 0); CP_COMMIT();

        for (int ch = 0; ch < nch; ch++) {
            const int st = ch & 1;
            if (ch + 1 < nch) { PV_LOAD(ch + 1, st ^ 1); CP_COMMIT(); CP_WAIT1(); }
            else              { CP_WAIT0(); }
            __syncthreads();

            unsigned Ah[2][4], Al[2][4], Bh[4][2], Bl[4][2];
#pragma unroll
            for (int m = 0; m < 2; m++) {
                unsigned rb = (unsigned)(wm * 32 + m * 16) * (PITCH * 4u);
                ldsm_x4(Ah[m][0], Ah[m][1], Ah[m][2], Ah[m][3],
                        baseSU + (st * 2 + 0) * (1536 * 4u) + rb + lo16);
                ldsm_x4(Al[m][0], Al[m][1], Al[m][2], Al[m][3],
                        baseSU + (st * 2 + 1) * (1536 * 4u) + rb + lo16);
            }
#pragma unroll
            for (int p = 0; p < 2; p++) {
                unsigned rb = (unsigned)(wn * 32 + p * 16) * (PITCH * 4u);
                ldsm_x4(Bh[2 * p][0], Bh[2 * p + 1][0], Bh[2 * p][1], Bh[2 * p + 1][1],
                        baseSU + (6144 * 4u) + (st * 2 + 0) * (768 * 4u) + rb + lo16);
                ldsm_x4(Bl[2 * p][0], Bl[2 * p + 1][0], Bl[2 * p][1], Bl[2 * p + 1][1],
                        baseSU + (6144 * 4u) + (st * 2 + 1) * (768 * 4u) + rb + lo16);
            }
#pragma unroll
            for (int m = 0; m < 2; m++)
#pragma unroll
                for (int n = 0; n < 4; n++) {
                    mma_bf16(acc[m][n], Ah[m], Bh[n]);
                    mma_bf16(acc[m][n], Ah[m], Bl[n]);
                    mma_bf16(acc[m][n], Al[m], Bh[n]);
                }
            __syncthreads();
        }
#undef PV_LOAD
#undef SA
#undef SB

        // epilogue: normalize by deterministic rowsum, streaming float2 stores
#pragma unroll
        for (int m = 0; m < 2; m++) {
            int ia = i0 + wm * 32 + m * 16 + g;
            int ib = ia + 8;
            float inv0 = 1.0f / row_sum((long)b * SS + ia, ia);
            float inv1 = 1.0f / row_sum((long)b * SS + ib, ib);
#pragma unroll
            for (int n = 0; n < 4; n++) {
                int da = d0 + wn * 32 + n * 8 + 2 * tq;
                __stcs(reinterpret_cast<float2*>(out + ((long)b * SS + ia) * DD + da),
                       make_float2(acc[m][n][0] * inv0, acc[m][n][1] * inv0));
                __stcs(reinterpret_cast<float2*>(out + ((long)b * SS + ib) * DD + da),
                       make_float2(acc[m][n][2] * inv1, acc[m][n][3] * inv1));
            }
        }
    } else if (full) {
        // ------------------ attn-row branch ------------------
        float* sw = reinterpret_cast<float*>(su);    // [8][512]
        const int wp   = threadIdx.x >> 5;
        const int row  = blockIdx.x * 8 + wp;        // 0 .. B*S-1
        const int lane = threadIdx.x & 31;

        const int i    = row & (SS - 1);
        const int cmax = i >> 3;

#pragma unroll
        for (int qd = 0; qd < 4; qd++) {
            int u = lane + 32 * qd;                  // uint2 index: values 4u..4u+3
            int base = 4 * u;
            uint2 H = *reinterpret_cast<const uint2*>(&g_whi[(long)row * NKP2 + 2 * u]);
            uint2 L = *reinterpret_cast<const uint2*>(&g_wlo[(long)row * NKP2 + 2 * u]);
            float2 h0 = __bfloat1622float2(*reinterpret_cast<__nv_bfloat162*>(&H.x));
            float2 h1 = __bfloat1622float2(*reinterpret_cast<__nv_bfloat162*>(&H.y));
            float2 l0 = __bfloat1622float2(*reinterpret_cast<__nv_bfloat162*>(&L.x));
            float2 l1 = __bfloat1622float2(*reinterpret_cast<__nv_bfloat162*>(&L.y));
            float w0 = (base     <= cmax) ? h0.x + l0.x : 0.f;
            float w1 = (base + 1 <= cmax) ? h0.y + l0.y : 0.f;
            float w2 = (base + 2 <= cmax) ? h1.x + l1.x : 0.f;
            float w3 = (base + 3 <= cmax) ? h1.y + l1.y : 0.f;
            *reinterpret_cast<float4*>(&sw[wp * 512 + base]) = make_float4(w0, w1, w2, w3);
        }
        const float inv = 1.0f / row_sum(row, i);    // c=0 always valid -> s>0
        __syncwarp();

        float4* arow = reinterpret_cast<float4*>(attn + (long)row * SS);
        const int half = lane >> 1;
        const bool even = (lane & 1) == 0;
#pragma unroll 4
        for (int gg = 0; gg < 32; gg++) {
            int t = lane + 32 * gg;                  // float4 index within row
            float x = 0.f;
            if (even) x = sw[wp * 512 + half + 16 * gg] * inv;   // zeros beyond cmax
            __stcs(&arow[t], make_float4(x, 0.f, 0.f, 0.f));
        }
    }
}

// ---------------------------------------------------------------------------
// Launch: 3 kernels, single stream (graph-capture-safe).
// ---------------------------------------------------------------------------
extern "C" void kernel_launch(void* const* d_in, const int* in_sizes, int n_in,
                              void* d_out, int out_size)
{
    const float* q = (const float*)d_in[0];
    const float* k = (const float*)d_in[1];
    const float* v = (const float*)d_in[2];
    float* out = (float*)d_out;

    const long n_out  = (long)BB * SS * DD;       //  8,388,608
    const long n_attn = (long)BB * SS * SS;       // 67,108,864
    const long n_mask = (long)SS * SS;            // 16,777,216
    const long need = n_out + n_attn + n_mask;

    const int full = ((long)out_size >= need) ? 1 : 0;
    float* attn = out + n_out;
    float* mask = attn + n_attn;

    // prep: q/k split (4096 blocks) + v transpose (1024) + mask rows (512)
    prep_fused_kernel<<<5632, 256>>>(q, k, v, mask, full);

    // QK GEMM: w (bf16 hi/lo) + deterministic rowsum partials
    qk_mma_kernel<<<dim3(NK / 64, SS / 128, BB), 256>>>();

    // attn rows (2048 blocks) first, then PV GEMM (1024 blocks), overlapped
    out_fused_kernel<<<3072, 256>>>(out, attn, full);
}

// round 15
// speedup vs baseline: 1.0778x; 1.0778x over previous
#include <cuda_runtime.h>
#include <cuda_bf16.h>

// Problem constants (StridedSparseAttention: B=4, S=4096, D=512, STRIDE=8)
#define BB 4
#define SS 4096
#define DD 512
#define NK 512          // number of strided keys = S/8
#define KSTRIDE 8
#define DP2 256         // DD/2 (b32 pairs per row)
#define NKP2 256        // NK/2
#define PITCH 12        // smem row pitch in uints (R11-validated)

#define SCALE 0.044194173824159216f   // 1/sqrt(512)

// Scratch (device globals — no allocations allowed). uint = packed bf16x2.
__device__ unsigned g_qhi[(long)BB * SS * DP2];
__device__ unsigned g_qlo[(long)BB * SS * DP2];
__device__ unsigned g_khi[BB * NK * DP2];
__device__ unsigned g_klo[BB * NK * DP2];
__device__ unsigned g_vthi[BB * DD * NKP2];      // vT[d][c] hi
__device__ unsigned g_vtlo[BB * DD * NKP2];
__device__ unsigned g_whi[(long)BB * SS * NKP2]; // UNnormalized exp(score), bf16 hi
__device__ unsigned g_wlo[(long)BB * SS * NKP2];
// Deterministic rowsum partials: 16 slots per row = [nt(0..7)][wn(0..1)].
__device__ float g_rspart[(long)BB * SS * 16];

// ---------------------------------------------------------------------------
// helpers
// ---------------------------------------------------------------------------
__device__ __forceinline__ void split2(float x, float y, unsigned& hi, unsigned& lo) {
    __nv_bfloat16 hx = __float2bfloat16_rn(x);
    __nv_bfloat16 hy = __float2bfloat16_rn(y);
    float rx = x - __bfloat162float(hx);
    float ry = y - __bfloat162float(hy);
    __nv_bfloat162 h2; h2.x = hx; h2.y = hy;
    __nv_bfloat162 l2; l2.x = __float2bfloat16_rn(rx); l2.y = __float2bfloat16_rn(ry);
    hi = *reinterpret_cast<unsigned*>(&h2);
    lo = *reinterpret_cast<unsigned*>(&l2);
}

__device__ __forceinline__ void mma_bf16(float* d, const unsigned* a, const unsigned* b) {
    asm volatile(
        "mma.sync.aligned.m16n8k16.row.col.f32.bf16.bf16.f32 "
        "{%0,%1,%2,%3},{%4,%5,%6,%7},{%8,%9},{%0,%1,%2,%3};\n"
        : "+f"(d[0]), "+f"(d[1]), "+f"(d[2]), "+f"(d[3])
        : "r"(a[0]), "r"(a[1]), "r"(a[2]), "r"(a[3]), "r"(b[0]), "r"(b[1]));
}

__device__ __forceinline__ void ldsm_x4(unsigned& r0, unsigned& r1,
                                        unsigned& r2, unsigned& r3, unsigned saddr) {
    asm volatile("ldmatrix.sync.aligned.m8n8.x4.shared.b16 {%0,%1,%2,%3}, [%4];"
                 : "=r"(r0), "=r"(r1), "=r"(r2), "=r"(r3) : "r"(saddr));
}

__device__ __forceinline__ void cp16(unsigned* smem, const unsigned* gmem) {
    unsigned s = (unsigned)__cvta_generic_to_shared(smem);
    asm volatile("cp.async.cg.shared.global [%0], [%1], 16;\n" :: "r"(s), "l"(gmem));
}
#define CP_COMMIT() asm volatile("cp.async.commit_group;\n")
#define CP_WAIT1()  asm volatile("cp.async.wait_group 1;\n")
#define CP_WAIT0()  asm volatile("cp.async.wait_group 0;\n")

// Deterministic rowsum: fixed-order reduction over the valid partial slots.
__device__ __forceinline__ float row_sum(long row, int i) {
    const int nv = ((i | 127) >> 9) + 1;         // valid nt tiles for this row
    const float* p = &g_rspart[row * 16];
    float s = 0.f;
    for (int j = 0; j < 2 * nv; j++) s += p[j];
    return s;
}

// ---------------------------------------------------------------------------
// Prep: ONLY the q/k split (the sole dependency of the QK GEMM).
// vT transpose + mask writing moved into qk's launch (they backfill its
// skipped tiles / tensor-idle slots instead of serializing ahead of it).
// ---------------------------------------------------------------------------
__global__ __launch_bounds__(256) void prep_qk_kernel(
    const float* __restrict__ q, const float* __restrict__ k)
{
    const long NQ  = (long)BB * SS * DP2;
    const long NKU = (long)BB * NK * DP2;
    const long str = 4096L * 256;
    long t0 = (long)blockIdx.x * 256 + threadIdx.x;

    for (long t = t0; t < NQ; t += str) {
        float2 f = reinterpret_cast<const float2*>(q)[t];
        unsigned hi, lo; split2(f.x, f.y, hi, lo);
        g_qhi[t] = hi; g_qlo[t] = lo;
    }
    for (long t = t0; t < NKU; t += str) {
        int b  = (int)(t / (NK * DP2));
        int r  = (int)((t / DP2) % NK);
        int dq = (int)(t % DP2);
        float2 f = reinterpret_cast<const float2*>(k)[((long)b * SS + KSTRIDE * r) * DP2 + dq];
        unsigned hi, lo; split2(f.x, f.y, hi, lo);
        g_khi[t] = hi; g_klo[t] = lo;
    }
}

// ---------------------------------------------------------------------------
// QK GEMM + vT transpose + mask rows, one launch (1D grid, 2560 blocks):
//   [0,1024):    GEMM tiles (R11 core: 2-stage cp.async, ldmatrix, causal skip)
//   [1024,2048): strided v -> vT[d][c] hi/lo (independent of q/k)
//   [2048,2560): mask rows of d_out (independent of everything)
// ---------------------------------------------------------------------------
__global__ __launch_bounds__(256) void qk_fused_kernel(
    const float* __restrict__ v, float* __restrict__ mask, int full)
{
    __shared__ unsigned su[9216];   // GEMM: sA 6144 + sB 3072 uints; vT: 1056 floats

    const int bx = blockIdx.x;

    if (bx >= 2048) {
        // ---------------- mask rows ----------------
        if (!full) return;
        const int i    = (bx - 2048) * 8 + (threadIdx.x >> 5);   // 0..S-1
        const int lane = threadIdx.x & 31;
        float4* mrow = reinterpret_cast<float4*>(mask + (long)i * SS);
        const int thr = i >> 2;                  // t <= thr && t even -> 1
        const bool even = (lane & 1) == 0;
#pragma unroll 4
        for (int gg = 0; gg < 32; gg++) {
            int t4 = lane + 32 * gg;
            float x = (even && t4 <= thr) ? 1.0f : 0.f;
            mrow[t4] = make_float4(x, 0.f, 0.f, 0.f);
        }
        return;
    }

    if (bx >= 1024) {
        // ---------------- V transpose (32x32 tiles) ----------------
        float (*sm)[33] = reinterpret_cast<float (*)[33]>(su);
        const int t   = bx - 1024;
        const int b   = t >> 8;
        const int rem = t & 255;
        const int c0  = (rem & 15) * 32;
        const int d0  = (rem >> 4) * 32;
        const int tid = threadIdx.x;
        const int r = tid >> 3;      // 0..31
        const int j = tid & 7;       // 0..7

        float4 f = *reinterpret_cast<const float4*>(
            v + ((long)b * SS + KSTRIDE * (c0 + r)) * DD + d0 + 4 * j);
        sm[r][4 * j + 0] = f.x; sm[r][4 * j + 1] = f.y;
        sm[r][4 * j + 2] = f.z; sm[r][4 * j + 3] = f.w;
        __syncthreads();

        float v0 = sm[4 * j + 0][r], v1 = sm[4 * j + 1][r];
        float v2 = sm[4 * j + 2][r], v3 = sm[4 * j + 3][r];
        unsigned h0, l0, h1, l1;
        split2(v0, v1, h0, l0);
        split2(v2, v3, h1, l1);
        long base = ((long)b * DD + d0 + r) * NKP2 + (c0 >> 1) + 2 * j;
        g_vthi[base] = h0; g_vthi[base + 1] = h1;
        g_vtlo[base] = l0; g_vtlo[base + 1] = l1;
        return;
    }

    // ---------------- GEMM tile (R11 core) ----------------
    const int b   = bx >> 8;
    const int rem = bx & 255;
    const int nt  = rem & 7;
    const int mt  = rem >> 3;
    const int i0  = mt * 128;
    const int c0  = nt * 64;
    if (8 * c0 > i0 + 127) return;   // fully masked tile

#define SA(st, h, i) su[((st) * 2 + (h)) * (128 * PITCH) + (i)]
#define SB(st, h, i) su[4 * 128 * PITCH + ((st) * 2 + (h)) * (64 * PITCH) + (i)]

    const int tid  = threadIdx.x;
    const int lane = tid & 31;
    const int wid  = tid >> 5;
    const int wm   = wid & 3;
    const int wn   = wid >> 2;
    const int g    = lane >> 2;
    const int tq   = lane & 3;

    const unsigned* qh = g_qhi + ((long)b * SS + i0) * DP2;
    const unsigned* ql = g_qlo + ((long)b * SS + i0) * DP2;
    const unsigned* kh = g_khi + ((long)b * NK + c0) * DP2;
    const unsigned* kl = g_klo + ((long)b * NK + c0) * DP2;

    const int lr = tid >> 1;          // 0..127
    const int lc = (tid & 1) * 4;     // 0 or 4

    const unsigned lo16   = ((lane & 15) * PITCH + (lane >> 4) * 4) * 4u;
    const unsigned baseSU = (unsigned)__cvta_generic_to_shared(&su[0]);
    const unsigned offB   = 4 * 128 * PITCH * 4u;

    float acc[2][4][4];
#pragma unroll
    for (int m = 0; m < 2; m++)
#pragma unroll
        for (int n = 0; n < 4; n++)
#pragma unroll
            for (int e = 0; e < 4; e++) acc[m][n][e] = 0.f;

#define QK_LOAD(ch, st)                                                          \
    do {                                                                         \
        int kb = (ch) * 8;                                                       \
        cp16(&SA(st, 0, lr * PITCH + lc), qh + (long)lr * DP2 + kb + lc);        \
        cp16(&SA(st, 1, lr * PITCH + lc), ql + (long)lr * DP2 + kb + lc);        \
        if (tid < 128) {                                                         \
            cp16(&SB(st, 0, lr * PITCH + lc), kh + (long)lr * DP2 + kb + lc);    \
            cp16(&SB(st, 1, lr * PITCH + lc), kl + (long)lr * DP2 + kb + lc);    \
        }                                                                        \
    } while (0)

    QK_LOAD(0, 0); CP_COMMIT();

    for (int ch = 0; ch < 32; ch++) {
        const int st = ch & 1;
        if (ch + 1 < 32) { QK_LOAD(ch + 1, st ^ 1); CP_COMMIT(); CP_WAIT1(); }
        else             { CP_WAIT0(); }
        __syncthreads();

        unsigned Ah[2][4], Al[2][4], Bh[4][2], Bl[4][2];
#pragma unroll
        for (int m = 0; m < 2; m++) {
            unsigned rb = (unsigned)(wm * 32 + m * 16) * (PITCH * 4u);
            ldsm_x4(Ah[m][0], Ah[m][1], Ah[m][2], Ah[m][3],
                    baseSU + (st * 2 + 0) * (128 * PITCH * 4u) + rb + lo16);
            ldsm_x4(Al[m][0], Al[m][1], Al[m][2], Al[m][3],
                    baseSU + (st * 2 + 1) * (128 * PITCH * 4u) + rb + lo16);
        }
#pragma unroll
        for (int p = 0; p < 2; p++) {
            unsigned rb = (unsigned)(wn * 32 + p * 16) * (PITCH * 4u);
            ldsm_x4(Bh[2 * p][0], Bh[2 * p + 1][0], Bh[2 * p][1], Bh[2 * p + 1][1],
                    baseSU + offB + (st * 2 + 0) * (64 * PITCH * 4u) + rb + lo16);
            ldsm_x4(Bl[2 * p][0], Bl[2 * p + 1][0], Bl[2 * p][1], Bl[2 * p + 1][1],
                    baseSU + offB + (st * 2 + 1) * (64 * PITCH * 4u) + rb + lo16);
        }
#pragma unroll
        for (int m = 0; m < 2; m++)
#pragma unroll
            for (int n = 0; n < 4; n++) {
                mma_bf16(acc[m][n], Ah[m], Bh[n]);
                mma_bf16(acc[m][n], Ah[m], Bl[n]);
                mma_bf16(acc[m][n], Al[m], Bh[n]);
            }
        __syncthreads();
    }
#undef QK_LOAD
#undef SA
#undef SB

    // epilogue: exp + causal predicate -> bf16 hi/lo; rowsum partial per (row,nt,wn)
#pragma unroll
    for (int m = 0; m < 2; m++) {
        int ia = i0 + wm * 32 + m * 16 + g;
        int ib = ia + 8;
        float p0 = 0.f, p1 = 0.f;
#pragma unroll
        for (int n = 0; n < 4; n++) {
            int ca = c0 + wn * 32 + n * 8 + 2 * tq;
            float w0 = (KSTRIDE * ca <= ia)       ? __expf(acc[m][n][0] * SCALE) : 0.f;
            float w1 = (KSTRIDE * (ca + 1) <= ia) ? __expf(acc[m][n][1] * SCALE) : 0.f;
            unsigned hi, lo; split2(w0, w1, hi, lo);
            long u0 = ((long)b * SS + ia) * NKP2 + (ca >> 1);
            g_whi[u0] = hi; g_wlo[u0] = lo;
            float w2 = (KSTRIDE * ca <= ib)       ? __expf(acc[m][n][2] * SCALE) : 0.f;
            float w3 = (KSTRIDE * (ca + 1) <= ib) ? __expf(acc[m][n][3] * SCALE) : 0.f;
            split2(w2, w3, hi, lo);
            long u1 = ((long)b * SS + ib) * NKP2 + (ca >> 1);
            g_whi[u1] = hi; g_wlo[u1] = lo;
            p0 += w0 + w1;
            p1 += w2 + w3;
        }
        p0 += __shfl_xor_sync(0xFFFFFFFFu, p0, 1);
        p0 += __shfl_xor_sync(0xFFFFFFFFu, p0, 2);
        p1 += __shfl_xor_sync(0xFFFFFFFFu, p1, 1);
        p1 += __shfl_xor_sync(0xFFFFFFFFu, p1, 2);
        if (tq == 0) {
            g_rspart[((long)b * SS + ia) * 16 + nt * 2 + wn] = p0;
            g_rspart[((long)b * SS + ib) * 16 + nt * 2 + wn] = p1;
        }
    }
}

// ---------------------------------------------------------------------------
// Fused output kernel (R11-exact):
//   blocks [0,1024):    PV GEMM tiles (cp.async + ldmatrix, heavy first)
//   blocks [1024,3072): attn rows of d_out (one warp per row)
// ---------------------------------------------------------------------------
__global__ __launch_bounds__(256) void out_fused_kernel(
    float* __restrict__ out, float* __restrict__ attn, int full)
{
    __shared__ unsigned su[9216];   // 36864 B union: pv(sA 24576 + sB 12288) / attn(16384)

    if (blockIdx.x < 1024) {
        // ------------------ PV branch ------------------
        const int idx = blockIdx.x;
        const int b   = idx >> 8;
        const int rem = idx & 255;
        const int nt  = rem & 7;
        const int mt  = 31 - (rem >> 3);   // heavy tiles first
        const int i0  = mt * 128;
        const int d0  = nt * 64;

#define SA(st, h, i) su[((st) * 2 + (h)) * 1536 + (i)]
#define SB(st, h, i) su[6144 + ((st) * 2 + (h)) * 768 + (i)]

        const int tid  = threadIdx.x;
        const int lane = tid & 31;
        const int wid  = tid >> 5;
        const int wm   = wid & 3;
        const int wn   = wid >> 2;
        const int g    = lane >> 2;
        const int tq   = lane & 3;

        const unsigned* wh = g_whi + ((long)b * SS + i0) * NKP2;
        const unsigned* wl = g_wlo + ((long)b * SS + i0) * NKP2;
        const unsigned* vh = g_vthi + ((long)b * DD + d0) * NKP2;
        const unsigned* vl = g_vtlo + ((long)b * DD + d0) * NKP2;

        const int lr = tid >> 1;
        const int lc = (tid & 1) * 4;

        const unsigned lo16   = ((lane & 15) * PITCH + (lane >> 4) * 4) * 4u;
        const unsigned baseSU = (unsigned)__cvta_generic_to_shared(&su[0]);

        float acc[2][4][4];
#pragma unroll
        for (int m = 0; m < 2; m++)
#pragma unroll
            for (int n = 0; n < 4; n++)
#pragma unroll
                for (int e = 0; e < 4; e++) acc[m][n][e] = 0.f;

        const int nch = mt + 1;   // k16 chunks with any valid key (<=32)

#define PV_LOAD(ch, st)                                                          \
    do {                                                                         \
        int kb = (ch) * 8;                                                       \
        cp16(&SA(st, 0, lr * PITCH + lc), wh + (long)lr * NKP2 + kb + lc);       \
        cp16(&SA(st, 1, lr * PITCH + lc), wl + (long)lr * NKP2 + kb + lc);       \
        if (tid < 128) {                                                         \
            cp16(&SB(st, 0, lr * PITCH + lc), vh + (long)lr * NKP2 + kb + lc);   \
            cp16(&SB(st, 1, lr * PITCH + lc), vl + (long)lr * NKP2 + kb + lc);   \
        }                                                                        \
    } while (0)

        PV_LOAD(0, 0); CP_COMMIT();

        for (int ch = 0; ch < nch; ch++) {
            const int st = ch & 1;
            if (ch + 1 < nch) { PV_LOAD(ch + 1, st ^ 1); CP_COMMIT(); CP_WAIT1(); }
            else              { CP_WAIT0(); }
            __syncthreads();

            unsigned Ah[2][4], Al[2][4], Bh[4][2], Bl[4][2];
#pragma unroll
            for (int m = 0; m < 2; m++) {
                unsigned rb = (unsigned)(wm * 32 + m * 16) * (PITCH * 4u);
                ldsm_x4(Ah[m][0], Ah[m][1], Ah[m][2], Ah[m][3],
                        baseSU + (st * 2 + 0) * (1536 * 4u) + rb + lo16);
                ldsm_x4(Al[m][0], Al[m][1], Al[m][2], Al[m][3],
                        baseSU + (st * 2 + 1) * (1536 * 4u) + rb + lo16);
            }
#pragma unroll
            for (int p = 0; p < 2; p++) {
                unsigned rb = (unsigned)(wn * 32 + p * 16) * (PITCH * 4u);
                ldsm_x4(Bh[2 * p][0], Bh[2 * p + 1][0], Bh[2 * p][1], Bh[2 * p + 1][1],
                        baseSU + (6144 * 4u) + (st * 2 + 0) * (768 * 4u) + rb + lo16);
                ldsm_x4(Bl[2 * p][0], Bl[2 * p + 1][0], Bl[2 * p][1], Bl[2 * p + 1][1],
                        baseSU + (6144 * 4u) + (st * 2 + 1) * (768 * 4u) + rb + lo16);
            }
#pragma unroll
            for (int m = 0; m < 2; m++)
#pragma unroll
                for (int n = 0; n < 4; n++) {
                    mma_bf16(acc[m][n], Ah[m], Bh[n]);
                    mma_bf16(acc[m][n], Ah[m], Bl[n]);
                    mma_bf16(acc[m][n], Al[m], Bh[n]);
                }
            __syncthreads();
        }
#undef PV_LOAD
#undef SA
#undef SB

        // epilogue: normalize by deterministic rowsum, float2 stores
#pragma unroll
        for (int m = 0; m < 2; m++) {
            int ia = i0 + wm * 32 + m * 16 + g;
            int ib = ia + 8;
            float inv0 = 1.0f / row_sum((long)b * SS + ia, ia);
            float inv1 = 1.0f / row_sum((long)b * SS + ib, ib);
#pragma unroll
            for (int n = 0; n < 4; n++) {
                int da = d0 + wn * 32 + n * 8 + 2 * tq;
                *reinterpret_cast<float2*>(out + ((long)b * SS + ia) * DD + da) =
                    make_float2(acc[m][n][0] * inv0, acc[m][n][1] * inv0);
                *reinterpret_cast<float2*>(out + ((long)b * SS + ib) * DD + da) =
                    make_float2(acc[m][n][2] * inv1, acc[m][n][3] * inv1);
            }
        }
    } else if (full) {
        // ------------------ attn-row branch ------------------
        float* sw = reinterpret_cast<float*>(su);    // [8][512]
        const int wp   = threadIdx.x >> 5;
        const int row  = (blockIdx.x - 1024) * 8 + wp;   // 0 .. B*S-1
        const int lane = threadIdx.x & 31;

        const int i    = row & (SS - 1);
        const int cmax = i >> 3;

#pragma unroll
        for (int qd = 0; qd < 4; qd++) {
            int u = lane + 32 * qd;                  // uint2 index: values 4u..4u+3
            int base = 4 * u;
            uint2 H = *reinterpret_cast<const uint2*>(&g_whi[(long)row * NKP2 + 2 * u]);
            uint2 L = *reinterpret_cast<const uint2*>(&g_wlo[(long)row * NKP2 + 2 * u]);
            float2 h0 = __bfloat1622float2(*reinterpret_cast<__nv_bfloat162*>(&H.x));
            float2 h1 = __bfloat1622float2(*reinterpret_cast<__nv_bfloat162*>(&H.y));
            float2 l0 = __bfloat1622float2(*reinterpret_cast<__nv_bfloat162*>(&L.x));
            float2 l1 = __bfloat1622float2(*reinterpret_cast<__nv_bfloat162*>(&L.y));
            float w0 = (base     <= cmax) ? h0.x + l0.x : 0.f;
            float w1 = (base + 1 <= cmax) ? h0.y + l0.y : 0.f;
            float w2 = (base + 2 <= cmax) ? h1.x + l1.x : 0.f;
            float w3 = (base + 3 <= cmax) ? h1.y + l1.y : 0.f;
            *reinterpret_cast<float4*>(&sw[wp * 512 + base]) = make_float4(w0, w1, w2, w3);
        }
        const float inv = 1.0f / row_sum(row, i);    // c=0 always valid -> s>0
        __syncwarp();

        float4* arow = reinterpret_cast<float4*>(attn + (long)row * SS);
        const int half = lane >> 1;
        const bool even = (lane & 1) == 0;
#pragma unroll 4
        for (int gg = 0; gg < 32; gg++) {
            int t = lane + 32 * gg;                  // float4 index within row
            float x = 0.f;
            if (even) x = sw[wp * 512 + half + 16 * gg] * inv;   // zeros beyond cmax
            arow[t] = make_float4(x, 0.f, 0.f, 0.f);
        }
    }
}

// ---------------------------------------------------------------------------
// Launch: 3 kernels, single stream (graph-capture-safe).
// ---------------------------------------------------------------------------
extern "C" void kernel_launch(void* const* d_in, const int* in_sizes, int n_in,
                              void* d_out, int out_size)
{
    const float* q = (const float*)d_in[0];
    const float* k = (const float*)d_in[1];
    const float* v = (const float*)d_in[2];
    float* out = (float*)d_out;

    const long n_out  = (long)BB * SS * DD;       //  8,388,608
    const long n_attn = (long)BB * SS * SS;       // 67,108,864
    const long n_mask = (long)SS * SS;            // 16,777,216
    const long need = n_out + n_attn + n_mask;

    const int full = ((long)out_size >= need) ? 1 : 0;
    float* attn = out + n_out;
    float* mask = attn + n_attn;

    // prep: q/k split only (vT + mask moved into qk's launch)
    prep_qk_kernel<<<4096, 256>>>(q, k);

    // QK GEMM tiles (1024) + vT transpose (1024) + mask rows (512)
    qk_fused_kernel<<<2560, 256>>>(v, mask, full);

    // PV GEMM (1024 blocks) + attn rows (2048 blocks), overlapped
    out_fused_kernel<<<3072, 256>>>(out, attn, full);
}

// round 16
// speedup vs baseline: 1.1102x; 1.0300x over previous
#include <cuda_runtime.h>
#include <cuda_bf16.h>

// Problem constants (StridedSparseAttention: B=4, S=4096, D=512, STRIDE=8)
#define BB 4
#define SS 4096
#define DD 512
#define NK 512          // number of strided keys = S/8
#define KSTRIDE 8
#define NKP2 256        // NK/2
#define PITCH 12        // smem row pitch in uints (R11-validated)

#define SCALE 0.044194173824159216f   // 1/sqrt(512)

// Scratch (device globals — no allocations allowed). uint = packed bf16x2.
__device__ unsigned g_vthi[BB * DD * NKP2];      // vT[d][c] hi
__device__ unsigned g_vtlo[BB * DD * NKP2];
__device__ unsigned g_whi[(long)BB * SS * NKP2]; // UNnormalized exp(score), bf16 hi
__device__ unsigned g_wlo[(long)BB * SS * NKP2];
// Deterministic rowsum partials: 16 slots per row = [nt(0..7)][wn(0..1)].
__device__ float g_rspart[(long)BB * SS * 16];

// ---------------------------------------------------------------------------
// helpers
// ---------------------------------------------------------------------------
__device__ __forceinline__ void split2(float x, float y, unsigned& hi, unsigned& lo) {
    __nv_bfloat16 hx = __float2bfloat16_rn(x);
    __nv_bfloat16 hy = __float2bfloat16_rn(y);
    float rx = x - __bfloat162float(hx);
    float ry = y - __bfloat162float(hy);
    __nv_bfloat162 h2; h2.x = hx; h2.y = hy;
    __nv_bfloat162 l2; l2.x = __float2bfloat16_rn(rx); l2.y = __float2bfloat16_rn(ry);
    hi = *reinterpret_cast<unsigned*>(&h2);
    lo = *reinterpret_cast<unsigned*>(&l2);
}

__device__ __forceinline__ void mma_bf16(float* d, const unsigned* a, const unsigned* b) {
    asm volatile(
        "mma.sync.aligned.m16n8k16.row.col.f32.bf16.bf16.f32 "
        "{%0,%1,%2,%3},{%4,%5,%6,%7},{%8,%9},{%0,%1,%2,%3};\n"
        : "+f"(d[0]), "+f"(d[1]), "+f"(d[2]), "+f"(d[3])
        : "r"(a[0]), "r"(a[1]), "r"(a[2]), "r"(a[3]), "r"(b[0]), "r"(b[1]));
}

__device__ __forceinline__ void ldsm_x4(unsigned& r0, unsigned& r1,
                                        unsigned& r2, unsigned& r3, unsigned saddr) {
    asm volatile("ldmatrix.sync.aligned.m8n8.x4.shared.b16 {%0,%1,%2,%3}, [%4];"
                 : "=r"(r0), "=r"(r1), "=r"(r2), "=r"(r3) : "r"(saddr));
}

__device__ __forceinline__ void cp16(unsigned* smem, const unsigned* gmem) {
    unsigned s = (unsigned)__cvta_generic_to_shared(smem);
    asm volatile("cp.async.cg.shared.global [%0], [%1], 16;\n" :: "r"(s), "l"(gmem));
}
#define CP_COMMIT() asm volatile("cp.async.commit_group;\n")
#define CP_WAIT1()  asm volatile("cp.async.wait_group 1;\n")
#define CP_WAIT0()  asm volatile("cp.async.wait_group 0;\n")

// Deterministic rowsum: fixed-order reduction over the valid partial slots.
__device__ __forceinline__ float row_sum(long row, int i) {
    const int nv = ((i | 127) >> 9) + 1;         // valid nt tiles for this row
    const float* p = &g_rspart[row * 16];
    float s = 0.f;
    for (int j = 0; j < 2 * nv; j++) s += p[j];
    return s;
}

// ---------------------------------------------------------------------------
// QK GEMM (with IN-KERNEL fp32->bf16hi/lo split) + vT transpose + mask rows.
// One launch (1D grid, 2560 blocks):
//   [0,1024):    GEMM tiles: register-prefetch fp32 loads, inline split2 -> smem,
//                2-stage buffers, ldmatrix + split-bf16 mma, causal skip.
//   [1024,2048): strided v -> vT[d][c] hi/lo (independent)
//   [2048,2560): mask rows of d_out (independent)
// ---------------------------------------------------------------------------
__global__ __launch_bounds__(256) void qk_fused_kernel(
    const float* __restrict__ q, const float* __restrict__ k,
    const float* __restrict__ v, float* __restrict__ mask, int full)
{
    __shared__ unsigned su[9216];   // GEMM: sA 6144 + sB 3072 uints; vT: 1056 floats

    const int bx = blockIdx.x;

    if (bx >= 2048) {
        // ---------------- mask rows ----------------
        if (!full) return;
        const int i    = (bx - 2048) * 8 + (threadIdx.x >> 5);   // 0..S-1
        const int lane = threadIdx.x & 31;
        float4* mrow = reinterpret_cast<float4*>(mask + (long)i * SS);
        const int thr = i >> 2;                  // t <= thr && t even -> 1
        const bool even = (lane & 1) == 0;
#pragma unroll 4
        for (int gg = 0; gg < 32; gg++) {
            int t4 = lane + 32 * gg;
            float x = (even && t4 <= thr) ? 1.0f : 0.f;
            mrow[t4] = make_float4(x, 0.f, 0.f, 0.f);
        }
        return;
    }

    if (bx >= 1024) {
        // ---------------- V transpose (32x32 tiles) ----------------
        float (*sm)[33] = reinterpret_cast<float (*)[33]>(su);
        const int t   = bx - 1024;
        const int b   = t >> 8;
        const int rem = t & 255;
        const int c0  = (rem & 15) * 32;
        const int d0  = (rem >> 4) * 32;
        const int tid = threadIdx.x;
        const int r = tid >> 3;      // 0..31
        const int j = tid & 7;       // 0..7

        float4 f = *reinterpret_cast<const float4*>(
            v + ((long)b * SS + KSTRIDE * (c0 + r)) * DD + d0 + 4 * j);
        sm[r][4 * j + 0] = f.x; sm[r][4 * j + 1] = f.y;
        sm[r][4 * j + 2] = f.z; sm[r][4 * j + 3] = f.w;
        __syncthreads();

        float v0 = sm[4 * j + 0][r], v1 = sm[4 * j + 1][r];
        float v2 = sm[4 * j + 2][r], v3 = sm[4 * j + 3][r];
        unsigned h0, l0, h1, l1;
        split2(v0, v1, h0, l0);
        split2(v2, v3, h1, l1);
        long base = ((long)b * DD + d0 + r) * NKP2 + (c0 >> 1) + 2 * j;
        g_vthi[base] = h0; g_vthi[base + 1] = h1;
        g_vtlo[base] = l0; g_vtlo[base + 1] = l1;
        return;
    }

    // ---------------- GEMM tile ----------------
    const int b   = bx >> 8;
    const int rem = bx & 255;
    const int nt  = rem & 7;
    const int mt  = rem >> 3;
    const int i0  = mt * 128;
    const int c0  = nt * 64;
    if (8 * c0 > i0 + 127) return;   // fully masked tile

#define SA(st, h, i) su[((st) * 2 + (h)) * (128 * PITCH) + (i)]
#define SB(st, h, i) su[4 * 128 * PITCH + ((st) * 2 + (h)) * (64 * PITCH) + (i)]

    const int tid  = threadIdx.x;
    const int lane = tid & 31;
    const int wid  = tid >> 5;
    const int wm   = wid & 3;
    const int wn   = wid >> 2;
    const int g    = lane >> 2;
    const int tq   = lane & 3;

    // fp32 source pointers
    const float* qp = q + ((long)b * SS + i0) * DD;
    const float* kp = k + (long)b * SS * DD;

    // Load thread mapping (per k16 chunk = 16 fp32 per row):
    //  A: 128 rows, 2 threads/row: lrA = tid>>1, lcA = (tid&1)*8 floats
    //  B:  64 rows, 4 threads/row: lrB = tid>>2, lcB = (tid&3)*4 floats
    const int lrA = tid >> 1;
    const int lcA = (tid & 1) * 8;
    const int lrB = tid >> 2;
    const int lcB = (tid & 3) * 4;
    const long kRow = (long)(KSTRIDE * (c0 + lrB)) * DD;

    const unsigned lo16   = ((lane & 15) * PITCH + (lane >> 4) * 4) * 4u;
    const unsigned baseSU = (unsigned)__cvta_generic_to_shared(&su[0]);
    const unsigned offB   = 4 * 128 * PITCH * 4u;

    float acc[2][4][4];
#pragma unroll
    for (int m = 0; m < 2; m++)
#pragma unroll
        for (int n = 0; n < 4; n++)
#pragma unroll
            for (int e = 0; e < 4; e++) acc[m][n][e] = 0.f;

    float a8[8];    // prefetched A fp32 (one chunk)
    float b4[4];    // prefetched B fp32

#define QK_FETCH(ch)                                                             \
    do {                                                                         \
        int kb = (ch) * 16;                                                      \
        const float* ar = qp + (long)lrA * DD + kb + lcA;                        \
        *reinterpret_cast<float4*>(a8)     = *reinterpret_cast<const float4*>(ar);     \
        *reinterpret_cast<float4*>(a8 + 4) = *reinterpret_cast<const float4*>(ar + 4); \
        const float* br = kp + kRow + kb + lcB;                                  \
        *reinterpret_cast<float4*>(b4) = *reinterpret_cast<const float4*>(br);   \
    } while (0)

#define QK_STORE(st)                                                             \
    do {                                                                         \
        unsigned h0, l0, h1, l1, h2, l2, h3, l3;                                 \
        split2(a8[0], a8[1], h0, l0); split2(a8[2], a8[3], h1, l1);              \
        split2(a8[4], a8[5], h2, l2); split2(a8[6], a8[7], h3, l3);              \
        *reinterpret_cast<uint4*>(&SA(st, 0, lrA * PITCH + (lcA >> 1))) =        \
            make_uint4(h0, h1, h2, h3);                                          \
        *reinterpret_cast<uint4*>(&SA(st, 1, lrA * PITCH + (lcA >> 1))) =        \
            make_uint4(l0, l1, l2, l3);                                          \
        unsigned bh0, bl0, bh1, bl1;                                             \
        split2(b4[0], b4[1], bh0, bl0); split2(b4[2], b4[3], bh1, bl1);          \
        *reinterpret_cast<uint2*>(&SB(st, 0, lrB * PITCH + (lcB >> 1))) =        \
            make_uint2(bh0, bh1);                                                \
        *reinterpret_cast<uint2*>(&SB(st, 1, lrB * PITCH + (lcB >> 1))) =        \
            make_uint2(bl0, bl1);                                                \
    } while (0)

    QK_FETCH(0);

    for (int ch = 0; ch < 32; ch++) {
        const int st = ch & 1;
        QK_STORE(st);                       // chunk ch regs -> stage st
        if (ch + 1 < 32) QK_FETCH(ch + 1);  // LDGs in flight during compute
        __syncthreads();

        unsigned Ah[2][4], Al[2][4], Bh[4][2], Bl[4][2];
#pragma unroll
        for (int m = 0; m < 2; m++) {
            unsigned rb = (unsigned)(wm * 32 + m * 16) * (PITCH * 4u);
            ldsm_x4(Ah[m][0], Ah[m][1], Ah[m][2], Ah[m][3],
                    baseSU + (st * 2 + 0) * (128 * PITCH * 4u) + rb + lo16);
            ldsm_x4(Al[m][0], Al[m][1], Al[m][2], Al[m][3],
                    baseSU + (st * 2 + 1) * (128 * PITCH * 4u) + rb + lo16);
        }
#pragma unroll
        for (int p = 0; p < 2; p++) {
            unsigned rb = (unsigned)(wn * 32 + p * 16) * (PITCH * 4u);
            ldsm_x4(Bh[2 * p][0], Bh[2 * p + 1][0], Bh[2 * p][1], Bh[2 * p + 1][1],
                    baseSU + offB + (st * 2 + 0) * (64 * PITCH * 4u) + rb + lo16);
            ldsm_x4(Bl[2 * p][0], Bl[2 * p + 1][0], Bl[2 * p][1], Bl[2 * p + 1][1],
                    baseSU + offB + (st * 2 + 1) * (64 * PITCH * 4u) + rb + lo16);
        }
#pragma unroll
        for (int m = 0; m < 2; m++)
#pragma unroll
            for (int n = 0; n < 4; n++) {
                mma_bf16(acc[m][n], Ah[m], Bh[n]);
                mma_bf16(acc[m][n], Ah[m], Bl[n]);
                mma_bf16(acc[m][n], Al[m], Bh[n]);
            }
        __syncthreads();
    }
#undef QK_FETCH
#undef QK_STORE
#undef SA
#undef SB

    // epilogue: exp + causal predicate -> bf16 hi/lo; rowsum partial per (row,nt,wn)
#pragma unroll
    for (int m = 0; m < 2; m++) {
        int ia = i0 + wm * 32 + m * 16 + g;
        int ib = ia + 8;
        float p0 = 0.f, p1 = 0.f;
#pragma unroll
        for (int n = 0; n < 4; n++) {
            int ca = c0 + wn * 32 + n * 8 + 2 * tq;
            float w0 = (KSTRIDE * ca <= ia)       ? __expf(acc[m][n][0] * SCALE) : 0.f;
            float w1 = (KSTRIDE * (ca + 1) <= ia) ? __expf(acc[m][n][1] * SCALE) : 0.f;
            unsigned hi, lo; split2(w0, w1, hi, lo);
            long u0 = ((long)b * SS + ia) * NKP2 + (ca >> 1);
            g_whi[u0] = hi; g_wlo[u0] = lo;
            float w2 = (KSTRIDE * ca <= ib)       ? __expf(acc[m][n][2] * SCALE) : 0.f;
            float w3 = (KSTRIDE * (ca + 1) <= ib) ? __expf(acc[m][n][3] * SCALE) : 0.f;
            split2(w2, w3, hi, lo);
            long u1 = ((long)b * SS + ib) * NKP2 + (ca >> 1);
            g_whi[u1] = hi; g_wlo[u1] = lo;
            p0 += w0 + w1;
            p1 += w2 + w3;
        }
        p0 += __shfl_xor_sync(0xFFFFFFFFu, p0, 1);
        p0 += __shfl_xor_sync(0xFFFFFFFFu, p0, 2);
        p1 += __shfl_xor_sync(0xFFFFFFFFu, p1, 1);
        p1 += __shfl_xor_sync(0xFFFFFFFFu, p1, 2);
        if (tq == 0) {
            g_rspart[((long)b * SS + ia) * 16 + nt * 2 + wn] = p0;
            g_rspart[((long)b * SS + ib) * 16 + nt * 2 + wn] = p1;
        }
    }
}

// ---------------------------------------------------------------------------
// Fused output kernel (R11/R15-exact):
//   blocks [0,1024):    PV GEMM tiles (cp.async + ldmatrix, heavy first)
//   blocks [1024,3072): attn rows of d_out (one warp per row)
// ---------------------------------------------------------------------------
__global__ __launch_bounds__(256) void out_fused_kernel(
    float* __restrict__ out, float* __restrict__ attn, int full)
{
    __shared__ unsigned su[9216];   // 36864 B union: pv(sA 24576 + sB 12288) / attn(16384)

    if (blockIdx.x < 1024) {
        // ------------------ PV branch ------------------
        const int idx = blockIdx.x;
        const int b   = idx >> 8;
        const int rem = idx & 255;
        const int nt  = rem & 7;
        const int mt  = 31 - (rem >> 3);   // heavy tiles first
        const int i0  = mt * 128;
        const int d0  = nt * 64;

#define SA(st, h, i) su[((st) * 2 + (h)) * 1536 + (i)]
#define SB(st, h, i) su[6144 + ((st) * 2 + (h)) * 768 + (i)]

        const int tid  = threadIdx.x;
        const int lane = tid & 31;
        const int wid  = tid >> 5;
        const int wm   = wid & 3;
        const int wn   = wid >> 2;
        const int g    = lane >> 2;
        const int tq   = lane & 3;

        const unsigned* wh = g_whi + ((long)b * SS + i0) * NKP2;
        const unsigned* wl = g_wlo + ((long)b * SS + i0) * NKP2;
        const unsigned* vh = g_vthi + ((long)b * DD + d0) * NKP2;
        const unsigned* vl = g_vtlo + ((long)b * DD + d0) * NKP2;

        const int lr = tid >> 1;
        const int lc = (tid & 1) * 4;

        const unsigned lo16   = ((lane & 15) * PITCH + (lane >> 4) * 4) * 4u;
        const unsigned baseSU = (unsigned)__cvta_generic_to_shared(&su[0]);

        float acc[2][4][4];
#pragma unroll
        for (int m = 0; m < 2; m++)
#pragma unroll
            for (int n = 0; n < 4; n++)
#pragma unroll
                for (int e = 0; e < 4; e++) acc[m][n][e] = 0.f;

        const int nch = mt + 1;   // k16 chunks with any valid key (<=32)

#define PV_LOAD(ch, st)                                                          \
    do {                                                                         \
        int kb = (ch) * 8;                                                       \
        cp16(&SA(st, 0, lr * PITCH + lc), wh + (long)lr * NKP2 + kb + lc);       \
        cp16(&SA(st, 1, lr * PITCH + lc), wl + (long)lr * NKP2 + kb + lc);       \
        if (tid < 128) {                                                         \
            cp16(&SB(st, 0, lr * PITCH + lc), vh + (long)lr * NKP2 + kb + lc);   \
            cp16(&SB(st, 1, lr * PITCH + lc), vl + (long)lr * NKP2 + kb + lc);   \
        }                                                                        \
    } while (0)

        PV_LOAD(0, 0); CP_COMMIT();

        for (int ch = 0; ch < nch; ch++) {
            const int st = ch & 1;
            if (ch + 1 < nch) { PV_LOAD(ch + 1, st ^ 1); CP_COMMIT(); CP_WAIT1(); }
            else              { CP_WAIT0(); }
            __syncthreads();

            unsigned Ah[2][4], Al[2][4], Bh[4][2], Bl[4][2];
#pragma unroll
            for (int m = 0; m < 2; m++) {
                unsigned rb = (unsigned)(wm * 32 + m * 16) * (PITCH * 4u);
                ldsm_x4(Ah[m][0], Ah[m][1], Ah[m][2], Ah[m][3],
                        baseSU + (st * 2 + 0) * (1536 * 4u) + rb + lo16);
                ldsm_x4(Al[m][0], Al[m][1], Al[m][2], Al[m][3],
                        baseSU + (st * 2 + 1) * (1536 * 4u) + rb + lo16);
            }
#pragma unroll
            for (int p = 0; p < 2; p++) {
                unsigned rb = (unsigned)(wn * 32 + p * 16) * (PITCH * 4u);
                ldsm_x4(Bh[2 * p][0], Bh[2 * p + 1][0], Bh[2 * p][1], Bh[2 * p + 1][1],
                        baseSU + (6144 * 4u) + (st * 2 + 0) * (768 * 4u) + rb + lo16);
                ldsm_x4(Bl[2 * p][0], Bl[2 * p + 1][0], Bl[2 * p][1], Bl[2 * p + 1][1],
                        baseSU + (6144 * 4u) + (st * 2 + 1) * (768 * 4u) + rb + lo16);
            }
#pragma unroll
            for (int m = 0; m < 2; m++)
#pragma unroll
                for (int n = 0; n < 4; n++) {
                    mma_bf16(acc[m][n], Ah[m], Bh[n]);
                    mma_bf16(acc[m][n], Ah[m], Bl[n]);
                    mma_bf16(acc[m][n], Al[m], Bh[n]);
                }
            __syncthreads();
        }
#undef PV_LOAD
#undef SA
#undef SB

        // epilogue: normalize by deterministic rowsum, float2 stores
#pragma unroll
        for (int m = 0; m < 2; m++) {
            int ia = i0 + wm * 32 + m * 16 + g;
            int ib = ia + 8;
            float inv0 = 1.0f / row_sum((long)b * SS + ia, ia);
            float inv1 = 1.0f / row_sum((long)b * SS + ib, ib);
#pragma unroll
            for (int n = 0; n < 4; n++) {
                int da = d0 + wn * 32 + n * 8 + 2 * tq;
                *reinterpret_cast<float2*>(out + ((long)b * SS + ia) * DD + da) =
                    make_float2(acc[m][n][0] * inv0, acc[m][n][1] * inv0);
                *reinterpret_cast<float2*>(out + ((long)b * SS + ib) * DD + da) =
                    make_float2(acc[m][n][2] * inv1, acc[m][n][3] * inv1);
            }
        }
    } else if (full) {
        // ------------------ attn-row branch ------------------
        float* sw = reinterpret_cast<float*>(su);    // [8][512]
        const int wp   = threadIdx.x >> 5;
        const int row  = (blockIdx.x - 1024) * 8 + wp;   // 0 .. B*S-1
        const int lane = threadIdx.x & 31;

        const int i    = row & (SS - 1);
        const int cmax = i >> 3;

#pragma unroll
        for (int qd = 0; qd < 4; qd++) {
            int u = lane + 32 * qd;                  // uint2 index: values 4u..4u+3
            int base = 4 * u;
            uint2 H = *reinterpret_cast<const uint2*>(&g_whi[(long)row * NKP2 + 2 * u]);
            uint2 L = *reinterpret_cast<const uint2*>(&g_wlo[(long)row * NKP2 + 2 * u]);
            float2 h0 = __bfloat1622float2(*reinterpret_cast<__nv_bfloat162*>(&H.x));
            float2 h1 = __bfloat1622float2(*reinterpret_cast<__nv_bfloat162*>(&H.y));
            float2 l0 = __bfloat1622float2(*reinterpret_cast<__nv_bfloat162*>(&L.x));
            float2 l1 = __bfloat1622float2(*reinterpret_cast<__nv_bfloat162*>(&L.y));
            float w0 = (base     <= cmax) ? h0.x + l0.x : 0.f;
            float w1 = (base + 1 <= cmax) ? h0.y + l0.y : 0.f;
            float w2 = (base + 2 <= cmax) ? h1.x + l1.x : 0.f;
            float w3 = (base + 3 <= cmax) ? h1.y + l1.y : 0.f;
            *reinterpret_cast<float4*>(&sw[wp * 512 + base]) = make_float4(w0, w1, w2, w3);
        }
        const float inv = 1.0f / row_sum(row, i);    // c=0 always valid -> s>0
        __syncwarp();

        float4* arow = reinterpret_cast<float4*>(attn + (long)row * SS);
        const int half = lane >> 1;
        const bool even = (lane & 1) == 0;
#pragma unroll 4
        for (int gg = 0; gg < 32; gg++) {
            int t = lane + 32 * gg;                  // float4 index within row
            float x = 0.f;
            if (even) x = sw[wp * 512 + half + 16 * gg] * inv;   // zeros beyond cmax
            arow[t] = make_float4(x, 0.f, 0.f, 0.f);
        }
    }
}

// ---------------------------------------------------------------------------
// Launch: 2 kernels, single stream (graph-capture-safe).
// ---------------------------------------------------------------------------
extern "C" void kernel_launch(void* const* d_in, const int* in_sizes, int n_in,
                              void* d_out, int out_size)
{
    const float* q = (const float*)d_in[0];
    const float* k = (const float*)d_in[1];
    const float* v = (const float*)d_in[2];
    float* out = (float*)d_out;

    const long n_out  = (long)BB * SS * DD;       //  8,388,608
    const long n_attn = (long)BB * SS * SS;       // 67,108,864
    const long n_mask = (long)SS * SS;            // 16,777,216
    const long need = n_out + n_attn + n_mask;

    const int full = ((long)out_size >= need) ? 1 : 0;
    float* attn = out + n_out;
    float* mask = attn + n_attn;

    // QK GEMM tiles w/ in-kernel split (1024) + vT transpose (1024) + mask (512)
    qk_fused_kernel<<<2560, 256>>>(q, k, v, mask, full);

    // PV GEMM (1024 blocks) + attn rows (2048 blocks), overlapped
    out_fused_kernel<<<3072, 256>>>(out, attn, full);
}

// round 17
// speedup vs baseline: 1.1241x; 1.0125x over previous
#include <cuda_runtime.h>
#include <cuda_bf16.h>

// Problem constants (StridedSparseAttention: B=4, S=4096, D=512, STRIDE=8)
#define BB 4
#define SS 4096
#define DD 512
#define NK 512          // number of strided keys = S/8
#define KSTRIDE 8
#define NKP2 256        // NK/2
#define PITCH 12        // smem row pitch in uints (R11-validated)

#define SCALE 0.044194173824159216f   // 1/sqrt(512)

// Scratch (device globals — no allocations allowed). uint = packed bf16x2.
__device__ unsigned g_vthi[BB * DD * NKP2];      // vT[d][c] hi
__device__ unsigned g_vtlo[BB * DD * NKP2];
__device__ unsigned g_whi[(long)BB * SS * NKP2]; // UNnormalized exp(score), bf16 hi
__device__ unsigned g_wlo[(long)BB * SS * NKP2];
// Deterministic rowsum partials: 16 slots per row = [nt(0..7)][wn(0..1)].
__device__ float g_rspart[(long)BB * SS * 16];

// ---------------------------------------------------------------------------
// helpers
// ---------------------------------------------------------------------------
__device__ __forceinline__ void split2(float x, float y, unsigned& hi, unsigned& lo) {
    __nv_bfloat16 hx = __float2bfloat16_rn(x);
    __nv_bfloat16 hy = __float2bfloat16_rn(y);
    float rx = x - __bfloat162float(hx);
    float ry = y - __bfloat162float(hy);
    __nv_bfloat162 h2; h2.x = hx; h2.y = hy;
    __nv_bfloat162 l2; l2.x = __float2bfloat16_rn(rx); l2.y = __float2bfloat16_rn(ry);
    hi = *reinterpret_cast<unsigned*>(&h2);
    lo = *reinterpret_cast<unsigned*>(&l2);
}

__device__ __forceinline__ void mma_bf16(float* d, const unsigned* a, const unsigned* b) {
    asm volatile(
        "mma.sync.aligned.m16n8k16.row.col.f32.bf16.bf16.f32 "
        "{%0,%1,%2,%3},{%4,%5,%6,%7},{%8,%9},{%0,%1,%2,%3};\n"
        : "+f"(d[0]), "+f"(d[1]), "+f"(d[2]), "+f"(d[3])
        : "r"(a[0]), "r"(a[1]), "r"(a[2]), "r"(a[3]), "r"(b[0]), "r"(b[1]));
}

__device__ __forceinline__ void ldsm_x4(unsigned& r0, unsigned& r1,
                                        unsigned& r2, unsigned& r3, unsigned saddr) {
    asm volatile("ldmatrix.sync.aligned.m8n8.x4.shared.b16 {%0,%1,%2,%3}, [%4];"
                 : "=r"(r0), "=r"(r1), "=r"(r2), "=r"(r3) : "r"(saddr));
}

__device__ __forceinline__ void cp16(unsigned* smem, const unsigned* gmem) {
    unsigned s = (unsigned)__cvta_generic_to_shared(smem);
    asm volatile("cp.async.cg.shared.global [%0], [%1], 16;\n" :: "r"(s), "l"(gmem));
}
#define CP_COMMIT() asm volatile("cp.async.commit_group;\n")
#define CP_WAIT1()  asm volatile("cp.async.wait_group 1;\n")
#define CP_WAIT0()  asm volatile("cp.async.wait_group 0;\n")

// Deterministic rowsum: fixed-order reduction over the valid partial slots.
__device__ __forceinline__ float row_sum(long row, int i) {
    const int nv = ((i | 127) >> 9) + 1;         // valid nt tiles for this row
    const float* p = &g_rspart[row * 16];
    float s = 0.f;
    for (int j = 0; j < 2 * nv; j++) s += p[j];
    return s;
}

// ---------------------------------------------------------------------------
// QK GEMM (with IN-KERNEL fp32->bf16hi/lo split) + vT transpose + mask rows.
// One launch (1D grid, 2560 blocks) — unchanged from R16 (passing).
// ---------------------------------------------------------------------------
__global__ __launch_bounds__(256) void qk_fused_kernel(
    const float* __restrict__ q, const float* __restrict__ k,
    const float* __restrict__ v, float* __restrict__ mask, int full)
{
    __shared__ unsigned su[9216];   // GEMM: sA 6144 + sB 3072 uints; vT: 1056 floats

    const int bx = blockIdx.x;

    if (bx >= 2048) {
        // ---------------- mask rows ----------------
        if (!full) return;
        const int i    = (bx - 2048) * 8 + (threadIdx.x >> 5);   // 0..S-1
        const int lane = threadIdx.x & 31;
        float4* mrow = reinterpret_cast<float4*>(mask + (long)i * SS);
        const int thr = i >> 2;                  // t <= thr && t even -> 1
        const bool even = (lane & 1) == 0;
#pragma unroll 4
        for (int gg = 0; gg < 32; gg++) {
            int t4 = lane + 32 * gg;
            float x = (even && t4 <= thr) ? 1.0f : 0.f;
            mrow[t4] = make_float4(x, 0.f, 0.f, 0.f);
        }
        return;
    }

    if (bx >= 1024) {
        // ---------------- V transpose (32x32 tiles) ----------------
        float (*sm)[33] = reinterpret_cast<float (*)[33]>(su);
        const int t   = bx - 1024;
        const int b   = t >> 8;
        const int rem = t & 255;
        const int c0  = (rem & 15) * 32;
        const int d0  = (rem >> 4) * 32;
        const int tid = threadIdx.x;
        const int r = tid >> 3;      // 0..31
        const int j = tid & 7;       // 0..7

        float4 f = *reinterpret_cast<const float4*>(
            v + ((long)b * SS + KSTRIDE * (c0 + r)) * DD + d0 + 4 * j);
        sm[r][4 * j + 0] = f.x; sm[r][4 * j + 1] = f.y;
        sm[r][4 * j + 2] = f.z; sm[r][4 * j + 3] = f.w;
        __syncthreads();

        float v0 = sm[4 * j + 0][r], v1 = sm[4 * j + 1][r];
        float v2 = sm[4 * j + 2][r], v3 = sm[4 * j + 3][r];
        unsigned h0, l0, h1, l1;
        split2(v0, v1, h0, l0);
        split2(v2, v3, h1, l1);
        long base = ((long)b * DD + d0 + r) * NKP2 + (c0 >> 1) + 2 * j;
        g_vthi[base] = h0; g_vthi[base + 1] = h1;
        g_vtlo[base] = l0; g_vtlo[base + 1] = l1;
        return;
    }

    // ---------------- GEMM tile ----------------
    const int b   = bx >> 8;
    const int rem = bx & 255;
    const int nt  = rem & 7;
    const int mt  = rem >> 3;
    const int i0  = mt * 128;
    const int c0  = nt * 64;
    if (8 * c0 > i0 + 127) return;   // fully masked tile

#define SA(st, h, i) su[((st) * 2 + (h)) * (128 * PITCH) + (i)]
#define SB(st, h, i) su[4 * 128 * PITCH + ((st) * 2 + (h)) * (64 * PITCH) + (i)]

    const int tid  = threadIdx.x;
    const int lane = tid & 31;
    const int wid  = tid >> 5;
    const int wm   = wid & 3;
    const int wn   = wid >> 2;
    const int g    = lane >> 2;
    const int tq   = lane & 3;

    const float* qp = q + ((long)b * SS + i0) * DD;
    const float* kp = k + (long)b * SS * DD;

    const int lrA = tid >> 1;
    const int lcA = (tid & 1) * 8;
    const int lrB = tid >> 2;
    const int lcB = (tid & 3) * 4;
    const long kRow = (long)(KSTRIDE * (c0 + lrB)) * DD;

    const unsigned lo16   = ((lane & 15) * PITCH + (lane >> 4) * 4) * 4u;
    const unsigned baseSU = (unsigned)__cvta_generic_to_shared(&su[0]);
    const unsigned offB   = 4 * 128 * PITCH * 4u;

    float acc[2][4][4];
#pragma unroll
    for (int m = 0; m < 2; m++)
#pragma unroll
        for (int n = 0; n < 4; n++)
#pragma unroll
            for (int e = 0; e < 4; e++) acc[m][n][e] = 0.f;

    float a8[8];
    float b4[4];

#define QK_FETCH(ch)                                                             \
    do {                                                                         \
        int kb = (ch) * 16;                                                      \
        const float* ar = qp + (long)lrA * DD + kb + lcA;                        \
        *reinterpret_cast<float4*>(a8)     = *reinterpret_cast<const float4*>(ar);     \
        *reinterpret_cast<float4*>(a8 + 4) = *reinterpret_cast<const float4*>(ar + 4); \
        const float* br = kp + kRow + kb + lcB;                                  \
        *reinterpret_cast<float4*>(b4) = *reinterpret_cast<const float4*>(br);   \
    } while (0)

#define QK_STORE(st)                                                             \
    do {                                                                         \
        unsigned h0, l0, h1, l1, h2, l2, h3, l3;                                 \
        split2(a8[0], a8[1], h0, l0); split2(a8[2], a8[3], h1, l1);              \
        split2(a8[4], a8[5], h2, l2); split2(a8[6], a8[7], h3, l3);              \
        *reinterpret_cast<uint4*>(&SA(st, 0, lrA * PITCH + (lcA >> 1))) =        \
            make_uint4(h0, h1, h2, h3);                                          \
        *reinterpret_cast<uint4*>(&SA(st, 1, lrA * PITCH + (lcA >> 1))) =        \
            make_uint4(l0, l1, l2, l3);                                          \
        unsigned bh0, bl0, bh1, bl1;                                             \
        split2(b4[0], b4[1], bh0, bl0); split2(b4[2], b4[3], bh1, bl1);          \
        *reinterpret_cast<uint2*>(&SB(st, 0, lrB * PITCH + (lcB >> 1))) =        \
            make_uint2(bh0, bh1);                                                \
        *reinterpret_cast<uint2*>(&SB(st, 1, lrB * PITCH + (lcB >> 1))) =        \
            make_uint2(bl0, bl1);                                                \
    } while (0)

    QK_FETCH(0);

    for (int ch = 0; ch < 32; ch++) {
        const int st = ch & 1;
        QK_STORE(st);
        if (ch + 1 < 32) QK_FETCH(ch + 1);
        __syncthreads();

        unsigned Ah[2][4], Al[2][4], Bh[4][2], Bl[4][2];
#pragma unroll
        for (int m = 0; m < 2; m++) {
            unsigned rb = (unsigned)(wm * 32 + m * 16) * (PITCH * 4u);
            ldsm_x4(Ah[m][0], Ah[m][1], Ah[m][2], Ah[m][3],
                    baseSU + (st * 2 + 0) * (128 * PITCH * 4u) + rb + lo16);
            ldsm_x4(Al[m][0], Al[m][1], Al[m][2], Al[m][3],
                    baseSU + (st * 2 + 1) * (128 * PITCH * 4u) + rb + lo16);
        }
#pragma unroll
        for (int p = 0; p < 2; p++) {
            unsigned rb = (unsigned)(wn * 32 + p * 16) * (PITCH * 4u);
            ldsm_x4(Bh[2 * p][0], Bh[2 * p + 1][0], Bh[2 * p][1], Bh[2 * p + 1][1],
                    baseSU + offB + (st * 2 + 0) * (64 * PITCH * 4u) + rb + lo16);
            ldsm_x4(Bl[2 * p][0], Bl[2 * p + 1][0], Bl[2 * p][1], Bl[2 * p + 1][1],
                    baseSU + offB + (st * 2 + 1) * (64 * PITCH * 4u) + rb + lo16);
        }
#pragma unroll
        for (int m = 0; m < 2; m++)
#pragma unroll
            for (int n = 0; n < 4; n++) {
                mma_bf16(acc[m][n], Ah[m], Bh[n]);
                mma_bf16(acc[m][n], Ah[m], Bl[n]);
                mma_bf16(acc[m][n], Al[m], Bh[n]);
            }
        __syncthreads();
    }
#undef QK_FETCH
#undef QK_STORE
#undef SA
#undef SB

    // epilogue: exp + causal predicate -> bf16 hi/lo; rowsum partial per (row,nt,wn)
#pragma unroll
    for (int m = 0; m < 2; m++) {
        int ia = i0 + wm * 32 + m * 16 + g;
        int ib = ia + 8;
        float p0 = 0.f, p1 = 0.f;
#pragma unroll
        for (int n = 0; n < 4; n++) {
            int ca = c0 + wn * 32 + n * 8 + 2 * tq;
            float w0 = (KSTRIDE * ca <= ia)       ? __expf(acc[m][n][0] * SCALE) : 0.f;
            float w1 = (KSTRIDE * (ca + 1) <= ia) ? __expf(acc[m][n][1] * SCALE) : 0.f;
            unsigned hi, lo; split2(w0, w1, hi, lo);
            long u0 = ((long)b * SS + ia) * NKP2 + (ca >> 1);
            g_whi[u0] = hi; g_wlo[u0] = lo;
            float w2 = (KSTRIDE * ca <= ib)       ? __expf(acc[m][n][2] * SCALE) : 0.f;
            float w3 = (KSTRIDE * (ca + 1) <= ib) ? __expf(acc[m][n][3] * SCALE) : 0.f;
            split2(w2, w3, hi, lo);
            long u1 = ((long)b * SS + ib) * NKP2 + (ca >> 1);
            g_whi[u1] = hi; g_wlo[u1] = lo;
            p0 += w0 + w1;
            p1 += w2 + w3;
        }
        p0 += __shfl_xor_sync(0xFFFFFFFFu, p0, 1);
        p0 += __shfl_xor_sync(0xFFFFFFFFu, p0, 2);
        p1 += __shfl_xor_sync(0xFFFFFFFFu, p1, 1);
        p1 += __shfl_xor_sync(0xFFFFFFFFu, p1, 2);
        if (tq == 0) {
            g_rspart[((long)b * SS + ia) * 16 + nt * 2 + wn] = p0;
            g_rspart[((long)b * SS + ib) * 16 + nt * 2 + wn] = p1;
        }
    }
}

// ---------------------------------------------------------------------------
// Fused output kernel, occupancy-capped to 4 CTAs/SM (64 regs):
//   blocks [0,1024):    PV GEMM tiles (B-fragments hoisted, A per-m)
//   blocks [1024,3072): attn rows of d_out (one warp per row)
// ---------------------------------------------------------------------------
__global__ __launch_bounds__(256, 4) void out_fused_kernel(
    float* __restrict__ out, float* __restrict__ attn, int full)
{
    __shared__ unsigned su[9216];   // 36864 B union: pv(sA 24576 + sB 12288) / attn(16384)

    if (blockIdx.x < 1024) {
        // ------------------ PV branch ------------------
        const int idx = blockIdx.x;
        const int b   = idx >> 8;
        const int rem = idx & 255;
        const int nt  = rem & 7;
        const int mt  = 31 - (rem >> 3);   // heavy tiles first
        const int i0  = mt * 128;
        const int d0  = nt * 64;

#define SA(st, h, i) su[((st) * 2 + (h)) * 1536 + (i)]
#define SB(st, h, i) su[6144 + ((st) * 2 + (h)) * 768 + (i)]

        const int tid  = threadIdx.x;
        const int lane = tid & 31;
        const int wid  = tid >> 5;
        const int wm   = wid & 3;
        const int wn   = wid >> 2;
        const int g    = lane >> 2;
        const int tq   = lane & 3;

        const unsigned* wh = g_whi + ((long)b * SS + i0) * NKP2;
        const unsigned* wl = g_wlo + ((long)b * SS + i0) * NKP2;
        const unsigned* vh = g_vthi + ((long)b * DD + d0) * NKP2;
        const unsigned* vl = g_vtlo + ((long)b * DD + d0) * NKP2;

        const int lr = tid >> 1;
        const int lc = (tid & 1) * 4;

        const unsigned lo16   = ((lane & 15) * PITCH + (lane >> 4) * 4) * 4u;
        const unsigned baseSU = (unsigned)__cvta_generic_to_shared(&su[0]);

        float acc[2][4][4];
#pragma unroll
        for (int m = 0; m < 2; m++)
#pragma unroll
            for (int n = 0; n < 4; n++)
#pragma unroll
                for (int e = 0; e < 4; e++) acc[m][n][e] = 0.f;

        const int nch = mt + 1;   // k16 chunks with any valid key (<=32)

#define PV_LOAD(ch, st)                                                          \
    do {                                                                         \
        int kb = (ch) * 8;                                                       \
        cp16(&SA(st, 0, lr * PITCH + lc), wh + (long)lr * NKP2 + kb + lc);       \
        cp16(&SA(st, 1, lr * PITCH + lc), wl + (long)lr * NKP2 + kb + lc);       \
        if (tid < 128) {                                                         \
            cp16(&SB(st, 0, lr * PITCH + lc), vh + (long)lr * NKP2 + kb + lc);   \
            cp16(&SB(st, 1, lr * PITCH + lc), vl + (long)lr * NKP2 + kb + lc);   \
        }                                                                        \
    } while (0)

        PV_LOAD(0, 0); CP_COMMIT();

        for (int ch = 0; ch < nch; ch++) {
            const int st = ch & 1;
            if (ch + 1 < nch) { PV_LOAD(ch + 1, st ^ 1); CP_COMMIT(); CP_WAIT1(); }
            else              { CP_WAIT0(); }
            __syncthreads();

            // B fragments hoisted (16 regs live), A fragments per-m (8 regs)
            unsigned Bh[4][2], Bl[4][2];
#pragma unroll
            for (int p = 0; p < 2; p++) {
                unsigned rb = (unsigned)(wn * 32 + p * 16) * (PITCH * 4u);
                ldsm_x4(Bh[2 * p][0], Bh[2 * p + 1][0], Bh[2 * p][1], Bh[2 * p + 1][1],
                        baseSU + (6144 * 4u) + (st * 2 + 0) * (768 * 4u) + rb + lo16);
                ldsm_x4(Bl[2 * p][0], Bl[2 * p + 1][0], Bl[2 * p][1], Bl[2 * p + 1][1],
                        baseSU + (6144 * 4u) + (st * 2 + 1) * (768 * 4u) + rb + lo16);
            }
#pragma unroll
            for (int m = 0; m < 2; m++) {
                unsigned Ah[4], Al[4];
                unsigned rb = (unsigned)(wm * 32 + m * 16) * (PITCH * 4u);
                ldsm_x4(Ah[0], Ah[1], Ah[2], Ah[3],
                        baseSU + (st * 2 + 0) * (1536 * 4u) + rb + lo16);
                ldsm_x4(Al[0], Al[1], Al[2], Al[3],
                        baseSU + (st * 2 + 1) * (1536 * 4u) + rb + lo16);
#pragma unroll
                for (int n = 0; n < 4; n++) {
                    mma_bf16(acc[m][n], Ah, Bh[n]);
                    mma_bf16(acc[m][n], Ah, Bl[n]);
                    mma_bf16(acc[m][n], Al, Bh[n]);
                }
            }
            __syncthreads();
        }
#undef PV_LOAD
#undef SA
#undef SB

        // epilogue: normalize by deterministic rowsum, float2 stores
#pragma unroll
        for (int m = 0; m < 2; m++) {
            int ia = i0 + wm * 32 + m * 16 + g;
            int ib = ia + 8;
            float inv0 = 1.0f / row_sum((long)b * SS + ia, ia);
            float inv1 = 1.0f / row_sum((long)b * SS + ib, ib);
#pragma unroll
            for (int n = 0; n < 4; n++) {
                int da = d0 + wn * 32 + n * 8 + 2 * tq;
                *reinterpret_cast<float2*>(out + ((long)b * SS + ia) * DD + da) =
                    make_float2(acc[m][n][0] * inv0, acc[m][n][1] * inv0);
                *reinterpret_cast<float2*>(out + ((long)b * SS + ib) * DD + da) =
                    make_float2(acc[m][n][2] * inv1, acc[m][n][3] * inv1);
            }
        }
    } else if (full) {
        // ------------------ attn-row branch ------------------
        float* sw = reinterpret_cast<float*>(su);    // [8][512]
        const int wp   = threadIdx.x >> 5;
        const int row  = (blockIdx.x - 1024) * 8 + wp;   // 0 .. B*S-1
        const int lane = threadIdx.x & 31;

        const int i    = row & (SS - 1);
        const int cmax = i >> 3;

#pragma unroll
        for (int qd = 0; qd < 4; qd++) {
            int u = lane + 32 * qd;                  // uint2 index: values 4u..4u+3
            int base = 4 * u;
            uint2 H = *reinterpret_cast<const uint2*>(&g_whi[(long)row * NKP2 + 2 * u]);
            uint2 L = *reinterpret_cast<const uint2*>(&g_wlo[(long)row * NKP2 + 2 * u]);
            float2 h0 = __bfloat1622float2(*reinterpret_cast<__nv_bfloat162*>(&H.x));
            float2 h1 = __bfloat1622float2(*reinterpret_cast<__nv_bfloat162*>(&H.y));
            float2 l0 = __bfloat1622float2(*reinterpret_cast<__nv_bfloat162*>(&L.x));
            float2 l1 = __bfloat1622float2(*reinterpret_cast<__nv_bfloat162*>(&L.y));
            float w0 = (base     <= cmax) ? h0.x + l0.x : 0.f;
            float w1 = (base + 1 <= cmax) ? h0.y + l0.y : 0.f;
            float w2 = (base + 2 <= cmax) ? h1.x + l1.x : 0.f;
            float w3 = (base + 3 <= cmax) ? h1.y + l1.y : 0.f;
            *reinterpret_cast<float4*>(&sw[wp * 512 + base]) = make_float4(w0, w1, w2, w3);
        }
        const float inv = 1.0f / row_sum(row, i);    // c=0 always valid -> s>0
        __syncwarp();

        float4* arow = reinterpret_cast<float4*>(attn + (long)row * SS);
        const int half = lane >> 1;
        const bool even = (lane & 1) == 0;
#pragma unroll 4
        for (int gg = 0; gg < 32; gg++) {
            int t = lane + 32 * gg;                  // float4 index within row
            float x = 0.f;
            if (even) x = sw[wp * 512 + half + 16 * gg] * inv;   // zeros beyond cmax
            arow[t] = make_float4(x, 0.f, 0.f, 0.f);
        }
    }
}

// ---------------------------------------------------------------------------
// Launch: 2 kernels, single stream (graph-capture-safe).
// ---------------------------------------------------------------------------
extern "C" void kernel_launch(void* const* d_in, const int* in_sizes, int n_in,
                              void* d_out, int out_size)
{
    const float* q = (const float*)d_in[0];
    const float* k = (const float*)d_in[1];
    const float* v = (const float*)d_in[2];
    float* out = (float*)d_out;

    const long n_out  = (long)BB * SS * DD;       //  8,388,608
    const long n_attn = (long)BB * SS * SS;       // 67,108,864
    const long n_mask = (long)SS * SS;            // 16,777,216
    const long need = n_out + n_attn + n_mask;

    const int full = ((long)out_size >= need) ? 1 : 0;
    float* attn = out + n_out;
    float* mask = attn + n_attn;

    // QK GEMM tiles w/ in-kernel split (1024) + vT transpose (1024) + mask (512)
    qk_fused_kernel<<<2560, 256>>>(q, k, v, mask, full);

    // PV GEMM (1024 blocks) + attn rows (2048 blocks), overlapped
    out_fused_kernel<<<3072, 256>>>(out, attn, full);
}